// round 9
// baseline (speedup 1.0000x reference)
#include <cuda_runtime.h>

#define NLAB   2047
#define NBATCH 2048

// Precomputed EXP of compact transition tables (gathered per launch, deterministic).
// eTup[n] = exp(transitions[parent(n), n, :, :])  (message n -> parent)
// eTdn[n] = exp(transitions[n, parent(n), :, :])  (message parent -> n)
__device__ float4 g_eTup[2048];
__device__ float4 g_eTdn[2048];

__global__ void prep_kernel(const float* __restrict__ trans) {
    int n = blockIdx.x * blockDim.x + threadIdx.x;
    if (n >= NLAB) return;
    if (n == 0) {
        g_eTup[0] = make_float4(1.f, 1.f, 1.f, 1.f);
        g_eTdn[0] = make_float4(1.f, 1.f, 1.f, 1.f);
        return;
    }
    int p = (n - 1) >> 1;
    const float4* t4 = reinterpret_cast<const float4*>(trans);
    float4 u = t4[(size_t)p * NLAB + n];   // dst=parent, src=n
    float4 d = t4[(size_t)n * NLAB + p];   // dst=n, src=parent
    g_eTup[n] = make_float4(__expf(u.x), __expf(u.y), __expf(u.z), __expf(u.w));
    g_eTdn[n] = make_float4(__expf(d.x), __expf(d.y), __expf(d.z), __expf(d.w));
}

__device__ __forceinline__ float2 f2add(float2 a, float2 b) {
    return make_float2(a.x + b.x, a.y + b.y);
}

// Both-destination-class logsumexp for one edge, sharing one exp.
__device__ __forceinline__ float2 lsepair2(float2 x, float4 eT) {
    float m  = fmaxf(x.x, x.y);
    float pd = __expf(fminf(x.x, x.y) - m);
    bool  f  = (x.x >= x.y);
    float a0 = f ? eT.x : eT.y, b0 = f ? eT.y : eT.x;
    float a1 = f ? eT.z : eT.w, b1 = f ? eT.w : eT.z;
    return make_float2(m + __logf(fmaf(pd, b0, a0)),
                       m + __logf(fmaf(pd, b1, a1)));
}

__device__ __forceinline__ float2 up_combine(float2 xl, float2 xr, float4 Tl, float4 Tr) {
    float2 a = lsepair2(xl, Tl);
    float2 b = lsepair2(xr, Tr);
    return make_float2(a.x + b.x, a.y + b.y);
}

__device__ __forceinline__ float lse2(float u, float v) {
    float m = fmaxf(u, v);
    return m + __logf(1.0f + __expf(fminf(u, v) - m));
}

__device__ __forceinline__ void emit2(float* __restrict__ orow, int n, float2 s) {
    float z = lse2(s.x, s.y);
    orow[n]        = s.x - z;
    orow[NLAB + n] = s.y - z;
}

__device__ __forceinline__ float2 ld_e(const float* __restrict__ er, int n) {
    return make_float2(er[n], er[NLAB + n]);
}

// shared parent-exp for both children on the way down
#define PARENT_EXP(tp, m, pd, f) \
    float m  = fmaxf((tp).x, (tp).y); \
    float pd = __expf(fminf((tp).x, (tp).y) - m); \
    bool  f  = ((tp).x >= (tp).y);

__device__ __forceinline__ float2 child_be(float m, float pd, bool f, float4 eT) {
    float a0 = f ? eT.x : eT.y, b0 = f ? eT.y : eT.x;
    float a1 = f ? eT.z : eT.w, b1 = f ? eT.w : eT.z;
    return make_float2(m + __logf(fmaf(pd, b0, a0)),
                       m + __logf(fmaf(pd, b1, a1)));
}

// TWO batch rows per CTA. Single smem array X per row: holds x = e + alpha on
// the way up, morphs to t = e + beta in place on the way down. Emissions are
// re-read from global where needed (L1/L2-hot). 16 KB smem, regs capped to 40
// -> 6 CTAs/SM.
__global__ void __launch_bounds__(256, 6) crf_kernel(const float* __restrict__ em,
                                                     float* __restrict__ out) {
    __shared__ float2 X[2][1024];

    const int tid = threadIdx.x;
    const size_t b0 = (size_t)(2 * blockIdx.x) * (2 * NLAB);
    const float* __restrict__ er0 = em + b0;
    const float* __restrict__ er1 = er0 + 2 * NLAB;
    float* __restrict__ o0 = out + b0;
    float* __restrict__ o1 = o0 + 2 * NLAB;

    // ---- up, leaf level: parents 511..1022 combine their two leaves (alpha=0)
    #pragma unroll
    for (int it = 0; it < 2; ++it) {
        int p = 511 + tid + 256 * it;
        int k = 2 * p + 1;                        // leaves k, k+1
        float4 Tl = g_eTup[k], Tr = g_eTup[k + 1];
        X[0][p] = f2add(ld_e(er0, p),
                        up_combine(ld_e(er0, k), ld_e(er0, k + 1), Tl, Tr));
        X[1][p] = f2add(ld_e(er1, p),
                        up_combine(ld_e(er1, k), ld_e(er1, k + 1), Tl, Tr));
    }
    __syncthreads();

    // ---- up, parent levels 8..0:  x[p] = e[p] + combine(x[children])
    #pragma unroll
    for (int pl = 8; pl >= 0; --pl) {
        const int base = (1 << pl) - 1;
        const int cnt  = 1 << pl;
        for (int i = tid; i < cnt; i += 256) {
            int p = base + i, c = 2 * p + 1;
            float4 Tl = g_eTup[c], Tr = g_eTup[c + 1];
            X[0][p] = f2add(ld_e(er0, p), up_combine(X[0][c], X[0][c + 1], Tl, Tr));
            X[1][p] = f2add(ld_e(er1, p), up_combine(X[1][c], X[1][c + 1], Tl, Tr));
        }
        __syncthreads();
    }

    // ---- root: emit score (beta=0 -> score = x), then t_root = e_root;
    //      push t to level-1 children.
    if (tid == 0) {
        #pragma unroll
        for (int r = 0; r < 2; ++r) {
            const float* __restrict__ er = r ? er1 : er0;
            float* __restrict__ orow     = r ? o1  : o0;
            emit2(orow, 0, X[r][0]);
            float2 t0 = ld_e(er, 0);
            PARENT_EXP(t0, m, pd, f)
            #pragma unroll
            for (int j = 1; j <= 2; ++j) {
                float2 be = child_be(m, pd, f, g_eTdn[j]);
                emit2(orow, j, f2add(X[r][j], be));
                X[r][j] = f2add(ld_e(er, j), be);     // x -> t
            }
        }
    }
    __syncthreads();

    // ---- down, parent levels 1..8: parent t in X; emit children, write t.
    #pragma unroll
    for (int pl = 1; pl <= 8; ++pl) {
        const int base = (1 << pl) - 1;
        const int cnt  = 1 << pl;
        for (int i = tid; i < cnt; i += 256) {
            int p = base + i, c = 2 * p + 1;
            float4 TL = g_eTdn[c], TR = g_eTdn[c + 1];
            #pragma unroll
            for (int r = 0; r < 2; ++r) {
                const float* __restrict__ er = r ? er1 : er0;
                float* __restrict__ orow     = r ? o1  : o0;
                float2 tp = X[r][p];
                PARENT_EXP(tp, m, pd, f)
                #pragma unroll
                for (int j = 0; j < 2; ++j) {
                    int n = c + j;
                    float2 be = child_be(m, pd, f, j ? TR : TL);
                    emit2(orow, n, f2add(X[r][n], be));
                    X[r][n] = f2add(ld_e(er, n), be); // x -> t
                }
            }
        }
        __syncthreads();
    }

    // ---- down, leaf level: parents 511..1022 push t to leaves (alpha = 0)
    #pragma unroll
    for (int it = 0; it < 2; ++it) {
        int p = 511 + tid + 256 * it;
        int c = 2 * p + 1;
        float4 TL = g_eTdn[c], TR = g_eTdn[c + 1];
        #pragma unroll
        for (int r = 0; r < 2; ++r) {
            const float* __restrict__ er = r ? er1 : er0;
            float* __restrict__ orow     = r ? o1  : o0;
            float2 tp = X[r][p];
            PARENT_EXP(tp, m, pd, f)
            #pragma unroll
            for (int j = 0; j < 2; ++j) {
                int n = c + j;
                float2 be = child_be(m, pd, f, j ? TR : TL);
                emit2(orow, n, f2add(ld_e(er, n), be));   // leaf: score = e + beta
            }
        }
    }
}

extern "C" void kernel_launch(void* const* d_in, const int* in_sizes, int n_in,
                              void* d_out, int out_size) {
    const float* em = (const float*)d_in[0];
    const float* tr = (const float*)d_in[1];
    if (n_in >= 2 && in_sizes[0] != NBATCH * 2 * NLAB) {
        em = (const float*)d_in[1];
        tr = (const float*)d_in[0];
    }
    prep_kernel<<<(NLAB + 255) / 256, 256>>>(tr);
    crf_kernel<<<NBATCH / 2, 256>>>(em, (float*)d_out);
}